// round 3
// baseline (speedup 1.0000x reference)
#include <cuda_runtime.h>
#include <cuda_fp16.h>
#include <cstdint>

// Problem constants (shapes fixed by the dataset)
#define MAX_N 100000
#define MAX_E 3200000
#define IN_DIM 256
#define HID 64
#define OUTD 10

// ---------------- scratch (device globals; no allocation allowed) ----------
__device__ int    g_is64;
__device__ int    g_rows[MAX_E];
__device__ int    g_cols[MAX_E];
__device__ float  g_dinv[MAX_N];       // weighted in-degree, then d^{-1/2} in place
__device__ int    g_count[MAX_N];      // unweighted in-degree (CSR histogram)
__device__ int    g_start[MAX_N];      // CSR row (by col) offsets, exclusive
__device__ int    g_cursor[MAX_N];     // scatter cursors
__device__ int    g_bsums[256];        // scan block sums
__device__ int2   g_csre[MAX_E];       // CSR entries: {src_row, bitcast(norm)}
__device__ __half g_h1[MAX_N * HID];   // GEMM outputs (fp16 gather payload)
__device__ float  g_h2[MAX_N * HID];   // aggregation outputs / next-layer inputs
__device__ float  g_h3[MAX_N * OUTD];

// ---------------- packed fp32x2 FMA (sm_100+) -------------------------------
__device__ __forceinline__ void fma2(float2& d, const float2& a, const float2& b) {
    unsigned long long dd = *(const unsigned long long*)&d;
    unsigned long long da = *(const unsigned long long*)&a;
    unsigned long long db = *(const unsigned long long*)&b;
    asm("fma.rn.f32x2 %0, %1, %2, %0;" : "+l"(dd) : "l"(da), "l"(db));
    d = *(float2*)&dd;
}

// ---------------- preprocessing --------------------------------------------
__global__ void detect_kernel(const unsigned int* __restrict__ w, long long nwords) {
    __shared__ int nz;
    if (threadIdx.x == 0) nz = 0;
    __syncthreads();
    for (long long i = 1 + 2 * (long long)threadIdx.x; i < nwords && i < 4096;
         i += 2 * (long long)blockDim.x)
        if (w[i] != 0u) nz = 1;
    __syncthreads();
    if (threadIdx.x == 0) g_is64 = (nz == 0) ? 1 : 0;
}

__global__ void zero_nd(int n) {
    int i = blockIdx.x * blockDim.x + threadIdx.x;
    if (i >= n) return;
    g_dinv[i] = 0.0f;
    g_count[i] = 0;
}

// Decode edges to int32, weighted degree (float) + histogram (int).
__global__ void convert_deg(const void* __restrict__ ei, const float* __restrict__ ew, int E) {
    int e = blockIdx.x * blockDim.x + threadIdx.x;
    if (e >= E) return;
    int r, c;
    if (g_is64) {
        const long long* p = (const long long*)ei;
        r = (int)p[e];
        c = (int)p[E + e];
    } else {
        const int* p = (const int*)ei;
        r = p[e];
        c = p[E + e];
    }
    g_rows[e] = r;
    g_cols[e] = c;
    atomicAdd(&g_dinv[c], ew[e]);
    atomicAdd(&g_count[c], 1);
}

__global__ void dinv_kernel(int n) {
    int i = blockIdx.x * blockDim.x + threadIdx.x;
    if (i >= n) return;
    float d = g_dinv[i];
    g_dinv[i] = (d > 0.0f) ? rsqrtf(fmaxf(d, 1e-12f)) : 0.0f;
}

__global__ void scan_block(int n) {
    __shared__ int warp_sums[32];
    int i = blockIdx.x * 1024 + threadIdx.x;
    int v = (i < n) ? g_count[i] : 0;
    int lane = threadIdx.x & 31, wid = threadIdx.x >> 5;
    int x = v;
#pragma unroll
    for (int o = 1; o < 32; o <<= 1) {
        int y = __shfl_up_sync(~0u, x, o);
        if (lane >= o) x += y;
    }
    if (lane == 31) warp_sums[wid] = x;
    __syncthreads();
    if (wid == 0) {
        int s = warp_sums[lane];
#pragma unroll
        for (int o = 1; o < 32; o <<= 1) {
            int y = __shfl_up_sync(~0u, s, o);
            if (lane >= o) s += y;
        }
        warp_sums[lane] = s;
    }
    __syncthreads();
    int base = (wid > 0) ? warp_sums[wid - 1] : 0;
    int incl = x + base;
    if (i < n) g_start[i] = incl - v;
    if (threadIdx.x == 1023) g_bsums[blockIdx.x] = incl;
}

__global__ void scan_sums(int nb) {
    if (threadIdx.x != 0 || blockIdx.x != 0) return;
    int run = 0;
    for (int b = 0; b < nb; b++) {
        int t = g_bsums[b];
        g_bsums[b] = run;
        run += t;
    }
}

__global__ void add_offsets(int n) {
    int i = blockIdx.x * blockDim.x + threadIdx.x;
    if (i >= n) return;
    int s = g_start[i] + g_bsums[i >> 10];
    g_start[i] = s;
    g_cursor[i] = s;
}

__global__ void scatter_csr(const float* __restrict__ ew, int E) {
    int e = blockIdx.x * blockDim.x + threadIdx.x;
    if (e >= E) return;
    int r = g_rows[e], c = g_cols[e];
    float w = g_dinv[r] * ew[e] * g_dinv[c];
    int p = atomicAdd(&g_cursor[c], 1);
    g_csre[p] = make_int2(r, __float_as_int(w));
}

// ---- tiled SGEMM w/ packed f32x2 FMA: C[M][64] = A[M][K] @ W[64][K]^T ------
// Output stored as fp16 (gather payload).
template <int K>
__global__ void gemm64h(const float* __restrict__ A, const float* __restrict__ W,
                        __half* __restrict__ C, int M) {
    __shared__ float2 As2[16][64];   // duplicated a: (a,a)
    __shared__ float  Bs[16][64];
    int tid = threadIdx.x;            // 256 threads
    int tx = tid & 15, ty = tid >> 4; // 16 x 16
    int m0 = blockIdx.x * 64;
    float2 acc[4][2];
#pragma unroll
    for (int i = 0; i < 4; i++) {
        acc[i][0] = make_float2(0.f, 0.f);
        acc[i][1] = make_float2(0.f, 0.f);
    }

    for (int k0 = 0; k0 < K; k0 += 16) {
        {   // load A tile 64x16 (duplicated-transposed into As2[k][m] = (a,a))
            int row = tid >> 2, kq = tid & 3;
            float4 v = make_float4(0.f, 0.f, 0.f, 0.f);
            if (m0 + row < M)
                v = *(const float4*)(A + (size_t)(m0 + row) * K + k0 + kq * 4);
            As2[kq * 4 + 0][row] = make_float2(v.x, v.x);
            As2[kq * 4 + 1][row] = make_float2(v.y, v.y);
            As2[kq * 4 + 2][row] = make_float2(v.z, v.z);
            As2[kq * 4 + 3][row] = make_float2(v.w, v.w);
        }
        {   // load W tile 64x16 (transposed into Bs[k][n])
            int n = tid >> 2, kq = tid & 3;
            float4 v = *(const float4*)(W + (size_t)n * K + k0 + kq * 4);
            Bs[kq * 4 + 0][n] = v.x;
            Bs[kq * 4 + 1][n] = v.y;
            Bs[kq * 4 + 2][n] = v.z;
            Bs[kq * 4 + 3][n] = v.w;
        }
        __syncthreads();
#pragma unroll
        for (int k = 0; k < 16; k++) {
            float4 b = *(const float4*)&Bs[k][tx * 4];
            float2 b01 = make_float2(b.x, b.y);
            float2 b23 = make_float2(b.z, b.w);
#pragma unroll
            for (int i = 0; i < 4; i++) {
                float2 ad = As2[k][ty * 4 + i];
                fma2(acc[i][0], ad, b01);
                fma2(acc[i][1], ad, b23);
            }
        }
        __syncthreads();
    }
#pragma unroll
    for (int i = 0; i < 4; i++) {
        int row = m0 + ty * 4 + i;
        if (row < M) {
            __half2 p0 = __floats2half2_rn(acc[i][0].x, acc[i][0].y);
            __half2 p1 = __floats2half2_rn(acc[i][1].x, acc[i][1].y);
            int2 st = make_int2(*(int*)&p0, *(int*)&p1);
            *(int2*)(C + (size_t)row * 64 + tx * 4) = st;
        }
    }
}

// C[M][10] = A[M][64] @ W[10][64]^T, one thread per row (fp32 in/out)
__global__ void gemm_k64_n10(const float* __restrict__ A, const float* __restrict__ W,
                             float* __restrict__ C, int M) {
    __shared__ float Ws[OUTD * 64];
    for (int i = threadIdx.x; i < OUTD * 64; i += blockDim.x) Ws[i] = W[i];
    __syncthreads();
    int row = blockIdx.x * blockDim.x + threadIdx.x;
    if (row >= M) return;
    float acc[OUTD] = {};
    const float4* a4 = (const float4*)(A + (size_t)row * 64);
#pragma unroll
    for (int kq = 0; kq < 16; kq++) {
        float4 v = a4[kq];
#pragma unroll
        for (int o = 0; o < OUTD; o++) {
            acc[o] += v.x * Ws[o * 64 + kq * 4 + 0] + v.y * Ws[o * 64 + kq * 4 + 1] +
                      v.z * Ws[o * 64 + kq * 4 + 2] + v.w * Ws[o * 64 + kq * 4 + 3];
        }
    }
#pragma unroll
    for (int o = 0; o < OUTD; o++) C[(size_t)row * OUTD + o] = acc[o];
}

// ---------------- CSR gather SpMM, D=64, fp16 payload, fused bias(+relu) ---
// One warp per destination node; each lane owns 2 feature dims (one half2).
template <int RELU>
__global__ void spmm_gather64h(const __half2* __restrict__ H, const float* __restrict__ b,
                               float* __restrict__ out, int N, int E) {
    int warp = (int)((blockIdx.x * (long long)blockDim.x + threadIdx.x) >> 5);
    int lane = threadIdx.x & 31;
    if (warp >= N) return;
    int s = g_start[warp];
    int e = (warp == N - 1) ? E : g_start[warp + 1];
    float2 acc = make_float2(0.0f, 0.0f);
    int j = s;
    for (; j + 1 < e; j += 2) {
        int2 c0 = g_csre[j];
        int2 c1 = g_csre[j + 1];
        float w0 = __int_as_float(c0.y), w1 = __int_as_float(c1.y);
        float2 v0 = __half22float2(H[(size_t)c0.x * 32 + lane]);
        float2 v1 = __half22float2(H[(size_t)c1.x * 32 + lane]);
        acc.x += w0 * v0.x + w1 * v1.x;
        acc.y += w0 * v0.y + w1 * v1.y;
    }
    if (j < e) {
        int2 c0 = g_csre[j];
        float w0 = __int_as_float(c0.y);
        float2 v0 = __half22float2(H[(size_t)c0.x * 32 + lane]);
        acc.x += w0 * v0.x;
        acc.y += w0 * v0.y;
    }
    float2 bb = *(const float2*)(b + lane * 2);
    acc.x += bb.x; acc.y += bb.y;
    if (RELU) { acc.x = fmaxf(acc.x, 0.0f); acc.y = fmaxf(acc.y, 0.0f); }
    *(float2*)(out + (size_t)warp * 64 + lane * 2) = acc;
}

// CSR gather SpMM, D=10, fp32, fused bias. One warp per node; lanes 0..9.
__global__ void spmm_gather10(const float* __restrict__ H, const float* __restrict__ b,
                              float* __restrict__ out, int N, int E) {
    int warp = (int)((blockIdx.x * (long long)blockDim.x + threadIdx.x) >> 5);
    int lane = threadIdx.x & 31;
    if (warp >= N) return;
    int s = g_start[warp];
    int e = (warp == N - 1) ? E : g_start[warp + 1];
    float acc = 0.0f;
    for (int j = s; j < e; j++) {
        int2 c0 = g_csre[j];
        float w0 = __int_as_float(c0.y);
        float v = (lane < OUTD) ? H[(size_t)c0.x * OUTD + lane] : 0.0f;
        acc += w0 * v;
    }
    if (lane < OUTD) out[(size_t)warp * OUTD + lane] = acc + b[lane];
}

// ---------------- launch ---------------------------------------------------
static inline unsigned int cdiv(long long a, int b) { return (unsigned int)((a + b - 1) / b); }

extern "C" void kernel_launch(void* const* d_in, const int* in_sizes, int n_in,
                              void* d_out, int out_size) {
    const float* x  = (const float*)d_in[0];
    const void*  ei = d_in[1];
    const float* ew = (const float*)d_in[2];
    const float* W1 = (const float*)d_in[3];
    const float* b1 = (const float*)d_in[4];
    const float* W2 = (const float*)d_in[5];
    const float* b2 = (const float*)d_in[6];
    const float* W3 = (const float*)d_in[7];
    const float* b3 = (const float*)d_in[8];
    float* out = (float*)d_out;

    const int N = in_sizes[0] / IN_DIM;  // 100000
    const int E = in_sizes[1] / 2;       // 3200000
    (void)n_in; (void)out_size;

    __half* h1;
    float *h2, *h3;
    cudaGetSymbolAddress((void**)&h1, g_h1);
    cudaGetSymbolAddress((void**)&h2, g_h2);
    cudaGetSymbolAddress((void**)&h3, g_h3);

    const int nb_scan = (N + 1023) / 1024;

    // --- preprocessing: decode edges, degree, d^{-1/2}, CSR build -----------
    detect_kernel<<<1, 256>>>((const unsigned int*)ei, (long long)E * 2);
    zero_nd<<<cdiv(N, 256), 256>>>(N);
    convert_deg<<<cdiv(E, 256), 256>>>(ei, ew, E);
    dinv_kernel<<<cdiv(N, 256), 256>>>(N);
    scan_block<<<nb_scan, 1024>>>(N);
    scan_sums<<<1, 32>>>(nb_scan);
    add_offsets<<<cdiv(N, 256), 256>>>(N);
    scatter_csr<<<cdiv(E, 256), 256>>>(ew, E);

    // --- layer 1: h2 = relu(Anorm @ (x@W1^T) + b1) --------------------------
    gemm64h<IN_DIM><<<cdiv(N, 64), 256>>>(x, W1, h1, N);
    spmm_gather64h<1><<<cdiv((long long)N * 32, 256), 256>>>((const __half2*)h1, b1, h2, N, E);

    // --- layer 2 ------------------------------------------------------------
    gemm64h<HID><<<cdiv(N, 64), 256>>>(h2, W2, h1, N);
    spmm_gather64h<1><<<cdiv((long long)N * 32, 256), 256>>>((const __half2*)h1, b2, h2, N, E);

    // --- layer 3: out = Anorm @ (h2@W3^T) + b3 (no relu) --------------------
    gemm_k64_n10<<<cdiv(N, 128), 128>>>(h2, W3, h3, N);
    spmm_gather10<<<cdiv((long long)N * 32, 256), 256>>>(h3, b3, out, N, E);
}

// round 4
// speedup vs baseline: 1.1452x; 1.1452x over previous
#include <cuda_runtime.h>
#include <cuda_fp16.h>
#include <mma.h>
#include <cstdint>

using namespace nvcuda;

// Problem constants (shapes fixed by the dataset)
#define MAX_N 100000
#define MAX_NP 100032            // padded to multiple of 64 for wmma tiles
#define MAX_E 3200000
#define IN_DIM 256
#define HID 64
#define OUTD 10

// ---------------- scratch (device globals; no allocation allowed) ----------
__device__ int    g_is64;
__device__ int    g_rows[MAX_E];
__device__ int    g_cols[MAX_E];
__device__ float  g_dinv[MAX_N];       // weighted in-degree -> d^{-1/2} in place
__device__ int    g_count[MAX_N];      // unweighted in-degree (CSR histogram)
__device__ int    g_start[MAX_N];      // CSR offsets (by destination)
__device__ int    g_cursor[MAX_N];     // scatter cursors
__device__ int    g_bsums[256];        // scan block sums
__device__ int2   g_csre[MAX_E];       // CSR entries: {src_row, bitcast(norm)}
__device__ __half g_xh[MAX_NP * IN_DIM];   // fp16 input features (padded)
__device__ __half g_W1h[HID * IN_DIM];
__device__ __half g_W2h[HID * HID];
__device__ __half g_h1h[MAX_NP * HID];     // GEMM outputs (fp16)
__device__ __half g_h2h[MAX_NP * HID];     // aggregation outputs (fp16)
__device__ float  g_h3[MAX_N * OUTD];

// ---------------- preprocessing --------------------------------------------
// Zero degree arrays everywhere; block 0 additionally detects edge dtype
// (int64 iff all odd 32-bit words are zero).
__global__ void detect_zero(const unsigned int* __restrict__ w, long long nwords, int n) {
    int i = blockIdx.x * blockDim.x + threadIdx.x;
    if (i < n) {
        g_dinv[i] = 0.0f;
        g_count[i] = 0;
    }
    if (blockIdx.x == 0) {
        __shared__ int nz;
        if (threadIdx.x == 0) nz = 0;
        __syncthreads();
        for (long long j = 1 + 2 * (long long)threadIdx.x; j < nwords && j < 4096;
             j += 2 * (long long)blockDim.x)
            if (w[j] != 0u) nz = 1;
        __syncthreads();
        if (threadIdx.x == 0) g_is64 = (nz == 0) ? 1 : 0;
    }
}

// Convert x -> fp16 (padded rows zeroed); first blocks also convert W1/W2.
__global__ void convert_xw(const float* __restrict__ x, const float* __restrict__ W1,
                           const float* __restrict__ W2, int M) {
    int tid = blockIdx.x * blockDim.x + threadIdx.x;   // one float4 per thread
    const int PER_ROW = IN_DIM / 4;                    // 64
    int row = tid / PER_ROW;
    int c4 = (tid % PER_ROW) * 4;
    if (row < MAX_NP) {
        uint2 st;
        if (row < M) {
            float4 v = *(const float4*)(x + (size_t)row * IN_DIM + c4);
            __half2 a = __floats2half2_rn(v.x, v.y);
            __half2 b = __floats2half2_rn(v.z, v.w);
            st.x = *(unsigned*)&a;
            st.y = *(unsigned*)&b;
        } else {
            st.x = 0u; st.y = 0u;
        }
        *(uint2*)(g_xh + (size_t)row * IN_DIM + c4) = st;
    }
    // W1: 16384 elems, W2: 4096 elems (4 per thread)
    if (tid < (HID * IN_DIM + HID * HID) / 4) {
        int q = tid * 4;
        if (q < HID * IN_DIM) {
            float4 v = *(const float4*)(W1 + q);
            __half2 a = __floats2half2_rn(v.x, v.y);
            __half2 b = __floats2half2_rn(v.z, v.w);
            uint2 st = make_uint2(*(unsigned*)&a, *(unsigned*)&b);
            *(uint2*)(g_W1h + q) = st;
        } else {
            int q2 = q - HID * IN_DIM;
            float4 v = *(const float4*)(W2 + q2);
            __half2 a = __floats2half2_rn(v.x, v.y);
            __half2 b = __floats2half2_rn(v.z, v.w);
            uint2 st = make_uint2(*(unsigned*)&a, *(unsigned*)&b);
            *(uint2*)(g_W2h + q2) = st;
        }
    }
}

// Decode edges to int32, weighted degree (float) + histogram (int).
__global__ void convert_deg(const void* __restrict__ ei, const float* __restrict__ ew, int E) {
    int e = blockIdx.x * blockDim.x + threadIdx.x;
    if (e >= E) return;
    int r, c;
    if (g_is64) {
        const long long* p = (const long long*)ei;
        r = (int)p[e];
        c = (int)p[E + e];
    } else {
        const int* p = (const int*)ei;
        r = p[e];
        c = p[E + e];
    }
    g_rows[e] = r;
    g_cols[e] = c;
    atomicAdd(&g_dinv[c], ew[e]);
    atomicAdd(&g_count[c], 1);
}

// Block-local exclusive scan of g_count -> g_start + block totals; also
// invert degrees to d^{-1/2} in the same pass.
__global__ void scan_dinv(int n) {
    __shared__ int warp_sums[32];
    int i = blockIdx.x * 1024 + threadIdx.x;
    int v = (i < n) ? g_count[i] : 0;
    if (i < n) {
        float d = g_dinv[i];
        g_dinv[i] = (d > 0.0f) ? rsqrtf(fmaxf(d, 1e-12f)) : 0.0f;
    }
    int lane = threadIdx.x & 31, wid = threadIdx.x >> 5;
    int x = v;
#pragma unroll
    for (int o = 1; o < 32; o <<= 1) {
        int y = __shfl_up_sync(~0u, x, o);
        if (lane >= o) x += y;
    }
    if (lane == 31) warp_sums[wid] = x;
    __syncthreads();
    if (wid == 0) {
        int s = warp_sums[lane];
#pragma unroll
        for (int o = 1; o < 32; o <<= 1) {
            int y = __shfl_up_sync(~0u, s, o);
            if (lane >= o) s += y;
        }
        warp_sums[lane] = s;
    }
    __syncthreads();
    int base = (wid > 0) ? warp_sums[wid - 1] : 0;
    int incl = x + base;
    if (i < n) g_start[i] = incl - v;
    if (threadIdx.x == 1023) g_bsums[blockIdx.x] = incl;
}

// Parallel scan of block sums (nb <= 128), one block of 128 threads.
__global__ void scan_sums(int nb) {
    __shared__ int ws[4];
    int i = threadIdx.x;
    int v = (i < nb) ? g_bsums[i] : 0;
    int lane = i & 31, wid = i >> 5;
    int x = v;
#pragma unroll
    for (int o = 1; o < 32; o <<= 1) {
        int y = __shfl_up_sync(~0u, x, o);
        if (lane >= o) x += y;
    }
    if (lane == 31) ws[wid] = x;
    __syncthreads();
    int base = 0;
    for (int k = 0; k < wid; k++) base += ws[k];
    if (i < nb) g_bsums[i] = base + x - v;   // exclusive
}

__global__ void add_offsets(int n) {
    int i = blockIdx.x * blockDim.x + threadIdx.x;
    if (i >= n) return;
    int s = g_start[i] + g_bsums[i >> 10];
    g_start[i] = s;
    g_cursor[i] = s;
}

__global__ void scatter_csr(const float* __restrict__ ew, int E) {
    int e = blockIdx.x * blockDim.x + threadIdx.x;
    if (e >= E) return;
    int r = g_rows[e], c = g_cols[e];
    float w = g_dinv[r] * ew[e] * g_dinv[c];
    int p = atomicAdd(&g_cursor[c], 1);
    g_csre[p] = make_int2(r, __float_as_int(w));
}

// ---------------- wmma GEMM: C[M][64] = A[M][K] @ W[64][K]^T (fp16 in/out) --
// 4 warps per block; warp w computes rows [m0+16w, m0+16w+16) x 64 cols.
template <int K>
__global__ void gemm_wmma(const __half* __restrict__ A, const __half* __restrict__ Wh,
                          __half* __restrict__ C, int M) {
    __shared__ float cs[64 * 64];
    int warp = threadIdx.x >> 5;
    int m0 = blockIdx.x * 64;
    wmma::fragment<wmma::accumulator, 16, 16, 16, float> acc[4];
#pragma unroll
    for (int n = 0; n < 4; n++) wmma::fill_fragment(acc[n], 0.0f);
    wmma::fragment<wmma::matrix_a, 16, 16, 16, __half, wmma::row_major> fa;
    wmma::fragment<wmma::matrix_b, 16, 16, 16, __half, wmma::col_major> fb;
    const __half* arow = A + (size_t)(m0 + warp * 16) * K;
#pragma unroll
    for (int k = 0; k < K; k += 16) {
        wmma::load_matrix_sync(fa, arow + k, K);
#pragma unroll
        for (int n = 0; n < 4; n++) {
            wmma::load_matrix_sync(fb, Wh + (size_t)n * 16 * K + k, K);
            wmma::mma_sync(acc[n], fa, fb, acc[n]);
        }
    }
#pragma unroll
    for (int n = 0; n < 4; n++)
        wmma::store_matrix_sync(cs + warp * 16 * 64 + n * 16, acc[n], 64, wmma::mem_row_major);
    __syncthreads();
    // convert 64x64 fp32 tile to fp16 and store (half2 per thread-iter)
    for (int i = threadIdx.x; i < 64 * 32; i += 128) {
        int r = i >> 5;
        int p = i & 31;
        int row = m0 + r;
        if (row < M) {
            float2 v = *(float2*)&cs[r * 64 + p * 2];
            __half2 h = __floats2half2_rn(v.x, v.y);
            *(__half2*)(C + (size_t)row * 64 + p * 2) = h;
        }
    }
}

// C[M][10] = A[M][64] @ W[10][64]^T, fp16 A, fp32 W/out; one thread per row
__global__ void gemm_k64_n10(const __half* __restrict__ A, const float* __restrict__ W,
                             float* __restrict__ C, int M) {
    __shared__ float Ws[OUTD * 64];
    for (int i = threadIdx.x; i < OUTD * 64; i += blockDim.x) Ws[i] = W[i];
    __syncthreads();
    int row = blockIdx.x * blockDim.x + threadIdx.x;
    if (row >= M) return;
    float acc[OUTD] = {};
    const __half2* a2 = (const __half2*)(A + (size_t)row * 64);
#pragma unroll
    for (int kq = 0; kq < 32; kq++) {
        float2 v = __half22float2(a2[kq]);
#pragma unroll
        for (int o = 0; o < OUTD; o++)
            acc[o] += v.x * Ws[o * 64 + kq * 2 + 0] + v.y * Ws[o * 64 + kq * 2 + 1];
    }
#pragma unroll
    for (int o = 0; o < OUTD; o++) C[(size_t)row * OUTD + o] = acc[o];
}

// ---------------- CSR gather SpMM, D=64, fp16 in/out, fused bias(+relu) ----
// One warp per destination node; each lane owns 2 feature dims (one half2).
template <int RELU>
__global__ void spmm_gather64h(const __half2* __restrict__ H, const float* __restrict__ b,
                               __half2* __restrict__ out, int N, int E) {
    int warp = (int)((blockIdx.x * (long long)blockDim.x + threadIdx.x) >> 5);
    int lane = threadIdx.x & 31;
    if (warp >= N) return;
    int s = g_start[warp];
    int e = (warp == N - 1) ? E : g_start[warp + 1];
    float2 acc = make_float2(0.0f, 0.0f);
    int j = s;
    for (; j + 1 < e; j += 2) {
        int2 c0 = g_csre[j];
        int2 c1 = g_csre[j + 1];
        float w0 = __int_as_float(c0.y), w1 = __int_as_float(c1.y);
        float2 v0 = __half22float2(H[(size_t)c0.x * 32 + lane]);
        float2 v1 = __half22float2(H[(size_t)c1.x * 32 + lane]);
        acc.x += w0 * v0.x + w1 * v1.x;
        acc.y += w0 * v0.y + w1 * v1.y;
    }
    if (j < e) {
        int2 c0 = g_csre[j];
        float w0 = __int_as_float(c0.y);
        float2 v0 = __half22float2(H[(size_t)c0.x * 32 + lane]);
        acc.x += w0 * v0.x;
        acc.y += w0 * v0.y;
    }
    float2 bb = *(const float2*)(b + lane * 2);
    acc.x += bb.x; acc.y += bb.y;
    if (RELU) { acc.x = fmaxf(acc.x, 0.0f); acc.y = fmaxf(acc.y, 0.0f); }
    out[(size_t)warp * 32 + lane] = __floats2half2_rn(acc.x, acc.y);
}

// CSR gather SpMM, D=10, fp32, fused bias. One warp per node; lanes 0..9.
__global__ void spmm_gather10(const float* __restrict__ H, const float* __restrict__ b,
                              float* __restrict__ out, int N, int E) {
    int warp = (int)((blockIdx.x * (long long)blockDim.x + threadIdx.x) >> 5);
    int lane = threadIdx.x & 31;
    if (warp >= N) return;
    int s = g_start[warp];
    int e = (warp == N - 1) ? E : g_start[warp + 1];
    float acc = 0.0f;
    for (int j = s; j < e; j++) {
        int2 c0 = g_csre[j];
        float w0 = __int_as_float(c0.y);
        float v = (lane < OUTD) ? H[(size_t)c0.x * OUTD + lane] : 0.0f;
        acc += w0 * v;
    }
    if (lane < OUTD) out[(size_t)warp * OUTD + lane] = acc + b[lane];
}

// ---------------- launch ---------------------------------------------------
static inline unsigned int cdiv(long long a, int b) { return (unsigned int)((a + b - 1) / b); }

extern "C" void kernel_launch(void* const* d_in, const int* in_sizes, int n_in,
                              void* d_out, int out_size) {
    const float* x  = (const float*)d_in[0];
    const void*  ei = d_in[1];
    const float* ew = (const float*)d_in[2];
    const float* W1 = (const float*)d_in[3];
    const float* b1 = (const float*)d_in[4];
    const float* W2 = (const float*)d_in[5];
    const float* b2 = (const float*)d_in[6];
    const float* W3 = (const float*)d_in[7];
    const float* b3 = (const float*)d_in[8];
    float* out = (float*)d_out;

    const int N = in_sizes[0] / IN_DIM;  // 100000
    const int E = in_sizes[1] / 2;       // 3200000
    (void)n_in; (void)out_size;

    __half *xh, *W1h, *W2h, *h1h, *h2h;
    float* h3;
    cudaGetSymbolAddress((void**)&xh, g_xh);
    cudaGetSymbolAddress((void**)&W1h, g_W1h);
    cudaGetSymbolAddress((void**)&W2h, g_W2h);
    cudaGetSymbolAddress((void**)&h1h, g_h1h);
    cudaGetSymbolAddress((void**)&h2h, g_h2h);
    cudaGetSymbolAddress((void**)&h3, g_h3);

    const int nb_scan = (N + 1023) / 1024;

    // --- preprocessing + fp16 conversion ------------------------------------
    detect_zero<<<cdiv(N, 256), 256>>>((const unsigned int*)ei, (long long)E * 2, N);
    convert_xw<<<cdiv((long long)MAX_NP * (IN_DIM / 4), 256), 256>>>(x, W1, W2, N);
    convert_deg<<<cdiv(E, 256), 256>>>(ei, ew, E);
    scan_dinv<<<nb_scan, 1024>>>(N);
    scan_sums<<<1, 128>>>(nb_scan);
    add_offsets<<<cdiv(N, 256), 256>>>(N);
    scatter_csr<<<cdiv(E, 256), 256>>>(ew, E);

    // --- layer 1: h2 = relu(Anorm @ (x@W1^T) + b1) --------------------------
    gemm_wmma<IN_DIM><<<MAX_NP / 64, 128>>>(xh, W1h, h1h, N);
    spmm_gather64h<1><<<cdiv((long long)N * 32, 256), 256>>>(
        (const __half2*)h1h, b1, (__half2*)h2h, N, E);

    // --- layer 2 ------------------------------------------------------------
    gemm_wmma<HID><<<MAX_NP / 64, 128>>>(h2h, W2h, h1h, N);
    spmm_gather64h<1><<<cdiv((long long)N * 32, 256), 256>>>(
        (const __half2*)h1h, b2, (__half2*)h2h, N, E);

    // --- layer 3: out = Anorm @ (h2@W3^T) + b3 (no relu) --------------------
    gemm_k64_n10<<<cdiv(N, 128), 128>>>(h2h, W3, h3, N);
    spmm_gather10<<<cdiv((long long)N * 32, 256), 256>>>(h3, b3, out, N, E);
}